// round 14
// baseline (speedup 1.0000x reference)
#include <cuda_runtime.h>
#include <cstdint>
#include <math.h>

// Problem dims
#define Bn   64
#define Tn   1024
#define TWOK 512
#define En   128
#define Hh   256
#define FH   1024          // 4*H
#define BT   (Bn*Tn)       // 65536
#define KXC  264           // 2E+1 padded to multiple of 8
#define HROW 288           // skewed h row stride (4 chunks of 72 floats)

// ---------------- packed fp32x2 helpers ----------------
__device__ __forceinline__ void fma2(unsigned long long& acc,
                                     unsigned long long a,
                                     unsigned long long b) {
    asm("fma.rn.f32x2 %0, %1, %2, %0;" : "+l"(acc) : "l"(a), "l"(b));
}
__device__ __forceinline__ float2 unpk(unsigned long long v) {
    float2 r;
    asm("mov.b64 {%0, %1}, %2;" : "=f"(r.x), "=f"(r.y) : "l"(v));
    return r;
}
__device__ __forceinline__ float sigf(float x) {
    return fmaf(__tanhf(0.5f * x), 0.5f, 0.5f);
}

// ---------------- scratch (static device globals) ----------------
__device__ float g_s[BT];
__device__ float g_Pt[BT];
__device__ float g_Cin[Bn * 8 * TWOK];
__device__ float g_cl[(size_t)BT * TWOK];
__device__ float g_xc[(size_t)BT * KXC];
__device__ float g_WlP[KXC * FH];
__device__ float g_blP[FH];
__device__ float g_pre[(size_t)BT * FH];           // [t*64+b][FH] permuted cols
__device__ float g_H[(size_t)BT * Hh];             // [t][b][256] time-major
__device__ float g_Y[(size_t)BT * Hh];             // rows in t*64+b order
__device__ int   g_rbar[8 * 32];                   // row barriers (128B apart)

// ---------------- tiny kernels ----------------
__global__ void k_reset() {
    int i = threadIdx.x;
    if (i < 8 * 32) g_rbar[i] = 0;
}

__global__ void k_sums(const float* __restrict__ x) {
    int row  = blockIdx.x * 8 + (threadIdx.x >> 5);
    int lane = threadIdx.x & 31;
    const float4* xr = (const float4*)(x + (size_t)row * TWOK);
    float s = 0.f;
#pragma unroll
    for (int i = 0; i < 4; i++) {
        float4 v = xr[i * 32 + lane];
        s += v.x + v.y + v.z + v.w;
    }
#pragma unroll
    for (int o = 16; o; o >>= 1) s += __shfl_xor_sync(0xffffffffu, s, o);
    if (!lane) g_s[row] = s;
}

__global__ void k_delta(const float* __restrict__ delta,
                        const float* __restrict__ Wd,
                        const float* __restrict__ bd) {
    int i = blockIdx.x * 256 + threadIdx.x;
    float ed = expf(-(delta[i] * Wd[0] + bd[0]));
    float* xr = g_xc + (size_t)i * KXC;
    xr[256] = ed;
#pragma unroll
    for (int j = 257; j < KXC; j++) xr[j] = 0.f;
}

// ----- count scan: ONE serial pass + parallel apply -----
__global__ void k_scanA(const float* __restrict__ x) {
    int idx = blockIdx.x * 256 + threadIdx.x;
    int f = idx & 511, seg = (idx >> 9) & 7, b = idx >> 12;
    const float* sp = g_s + b * Tn + seg * 128;
    const float* xp = x    + ((size_t)b * Tn + seg * 128) * TWOK + f;
    float*       cp = g_cl + ((size_t)b * Tn + seg * 128) * TWOK + f;
    float c = 0.f;
#pragma unroll 4
    for (int tt = 0; tt < 128; tt++) {
        c = fmaf(sp[tt], c, xp[(size_t)tt * TWOK]);
        cp[(size_t)tt * TWOK] = c;
    }
}
__global__ void k_Pt() {
    int idx = blockIdx.x * 256 + threadIdx.x;
    if (idx >= Bn * 8) return;
    int b = idx >> 3, seg = idx & 7;
    const float* sp = g_s + b * Tn + seg * 128;
    float* pp = g_Pt + b * Tn + seg * 128;
    float p = 1.f;
    for (int tt = 0; tt < 128; tt++) { p *= sp[tt]; pp[tt] = p; }
}
__global__ void k_carry() {
    int idx = blockIdx.x * 256 + threadIdx.x;
    int b = idx >> 9, f = idx & 511;
    float c = 0.f;
#pragma unroll
    for (int j = 0; j < 8; j++) {
        g_Cin[(b * 8 + j) * 512 + f] = c;
        float P = g_Pt[b * Tn + j * 128 + 127];
        float Qe = g_cl[((size_t)b * Tn + j * 128 + 127) * TWOK + f];
        c = fmaf(P, c, Qe);
    }
}
__global__ void k_apply() {
    int gid = blockIdx.x * 256 + threadIdx.x;
    int row = gid >> 7, f4 = gid & 127;
    int b = row >> 10, t = row & 1023, seg = t >> 7;
    float A = g_Pt[row];
    float4* qp = (float4*)&g_cl[(size_t)row * TWOK + f4 * 4];
    float4 qv = *qp;
    float4 ci = *(const float4*)&g_Cin[((b << 3) + seg) * 512 + f4 * 4];
    qv.x = log1pf(fmaf(ci.x, A, qv.x));
    qv.y = log1pf(fmaf(ci.y, A, qv.y));
    qv.z = log1pf(fmaf(ci.z, A, qv.z));
    qv.w = log1pf(fmaf(ci.w, A, qv.w));
    *qp = qv;
}

__global__ void k_wlp(const float* __restrict__ Wl, const float* __restrict__ bl) {
    int i = blockIdx.x * 256 + threadIdx.x;
    if (i >= KXC * FH) return;
    int k = i / FH, jp = i % FH;
    int orig = (jp & 3) * 256 + (jp >> 2);
    g_WlP[i] = (k < 2 * En + 1) ? Wl[k * FH + orig] : 0.f;
    if (k == 0) g_blP[jp] = bl[orig];
}

// ---------------- fp32x2 SGEMM (register-pipelined inner loop) ----------------
// EPI 0: plain.  EPI 1: sigmoid*q (rows t*64+b).  EPI 2: row remap b*Tn+t -> t*64+b.
template <int EPI>
__global__ void __launch_bounds__(256, 1) sgemm(
    const float* __restrict__ A, int lda,
    const float* __restrict__ Bm, int ldb,
    float* __restrict__ C, int ldc, int coff,
    const float* __restrict__ bias,
    const float* __restrict__ q,
    int K) {
    __shared__ __align__(16) float2 As2[2][4][128];
    __shared__ __align__(16) float2 Bs2[2][4][128];
    const int row0 = blockIdx.x * 128, col0 = blockIdx.y * 128;
    const int tid = threadIdx.x;
    const int ar = tid >> 1, aq = tid & 1;
    const int w = tid >> 5, lane = tid & 31;
    const int bk2 = w >> 1, bc = (w & 1) * 64 + lane * 2;
    const int ty = tid >> 4, tx = tid & 15;

    const float* Ap  = A + (size_t)(row0 + ar) * lda + aq * 4;
    const float* Bp0 = Bm + col0 + bc;

    unsigned long long acc[8][8];
#pragma unroll
    for (int i = 0; i < 8; i++)
#pragma unroll
        for (int j = 0; j < 8; j++) acc[i][j] = 0ull;

    {
        float4 av = *(const float4*)Ap;
        float2 b0 = *(const float2*)(Bp0 + (size_t)(2 * bk2) * ldb);
        float2 b1 = *(const float2*)(Bp0 + (size_t)(2 * bk2 + 1) * ldb);
        As2[0][2 * aq][ar]     = make_float2(av.x, av.y);
        As2[0][2 * aq + 1][ar] = make_float2(av.z, av.w);
        *(float4*)&Bs2[0][bk2][bc] = make_float4(b0.x, b1.x, b0.y, b1.y);
    }
    __syncthreads();

    int buf = 0;
    for (int k0 = 0; k0 < K; k0 += 8) {
        const bool more = (k0 + 8 < K);
        float4 avn; float2 b0n, b1n;
        if (more) {
            avn = *(const float4*)(Ap + k0 + 8);
            b0n = *(const float2*)(Bp0 + (size_t)(k0 + 8 + 2 * bk2) * ldb);
            b1n = *(const float2*)(Bp0 + (size_t)(k0 + 8 + 2 * bk2 + 1) * ldb);
        }
        // ---- register-pipelined plane loop: prefetch kk2+1 before kk2's math ----
        ulonglong2 ca0 = *(const ulonglong2*)&As2[buf][0][ty * 8];
        ulonglong2 ca1 = *(const ulonglong2*)&As2[buf][0][ty * 8 + 2];
        ulonglong2 ca2 = *(const ulonglong2*)&As2[buf][0][ty * 8 + 4];
        ulonglong2 ca3 = *(const ulonglong2*)&As2[buf][0][ty * 8 + 6];
        ulonglong2 cb0 = *(const ulonglong2*)&Bs2[buf][0][tx * 8];
        ulonglong2 cb1 = *(const ulonglong2*)&Bs2[buf][0][tx * 8 + 2];
        ulonglong2 cb2 = *(const ulonglong2*)&Bs2[buf][0][tx * 8 + 4];
        ulonglong2 cb3 = *(const ulonglong2*)&Bs2[buf][0][tx * 8 + 6];
#pragma unroll
        for (int kk2 = 0; kk2 < 4; kk2++) {
            ulonglong2 na0, na1, na2, na3, nb0, nb1, nb2, nb3;
            if (kk2 < 3) {
                na0 = *(const ulonglong2*)&As2[buf][kk2 + 1][ty * 8];
                na1 = *(const ulonglong2*)&As2[buf][kk2 + 1][ty * 8 + 2];
                na2 = *(const ulonglong2*)&As2[buf][kk2 + 1][ty * 8 + 4];
                na3 = *(const ulonglong2*)&As2[buf][kk2 + 1][ty * 8 + 6];
                nb0 = *(const ulonglong2*)&Bs2[buf][kk2 + 1][tx * 8];
                nb1 = *(const ulonglong2*)&Bs2[buf][kk2 + 1][tx * 8 + 2];
                nb2 = *(const ulonglong2*)&Bs2[buf][kk2 + 1][tx * 8 + 4];
                nb3 = *(const ulonglong2*)&Bs2[buf][kk2 + 1][tx * 8 + 6];
            }
            unsigned long long aa[8] = {ca0.x, ca0.y, ca1.x, ca1.y,
                                        ca2.x, ca2.y, ca3.x, ca3.y};
            unsigned long long bb[8] = {cb0.x, cb0.y, cb1.x, cb1.y,
                                        cb2.x, cb2.y, cb3.x, cb3.y};
#pragma unroll
            for (int i = 0; i < 8; i++)
#pragma unroll
                for (int j = 0; j < 8; j++) fma2(acc[i][j], aa[i], bb[j]);
            if (kk2 < 3) {
                ca0 = na0; ca1 = na1; ca2 = na2; ca3 = na3;
                cb0 = nb0; cb1 = nb1; cb2 = nb2; cb3 = nb3;
            }
        }
        if (more) {
            As2[buf ^ 1][2 * aq][ar]     = make_float2(avn.x, avn.y);
            As2[buf ^ 1][2 * aq + 1][ar] = make_float2(avn.z, avn.w);
            *(float4*)&Bs2[buf ^ 1][bk2][bc] = make_float4(b0n.x, b1n.x, b0n.y, b1n.y);
        }
        __syncthreads();
        buf ^= 1;
    }

#pragma unroll
    for (int i = 0; i < 8; i++) {
        size_t r = (size_t)row0 + ty * 8 + i;
        size_t rout = r;
        if (EPI == 2) rout = ((r & 1023) << 6) + (r >> 10);   // b*Tn+t -> t*64+b
#pragma unroll
        for (int j = 0; j < 8; j++) {
            int c = col0 + tx * 8 + j;
            float2 p = unpk(acc[i][j]);
            float v = p.x + p.y + bias[c];
            if (EPI == 1) {
                size_t qr = ((size_t)(r & 63) << 10) + (r >> 6);
                v = q[qr * 256 + c] * sigf(v);
            }
            C[rout * ldc + coff + c] = v;
        }
    }
}

// ---------------- persistent LSTM scan: R11 known-good (1-col, R9 barrier) ----------------
__global__ void __launch_bounds__(256, 1) k_lstm(
    const float* __restrict__ Ul,
    const float* __restrict__ pre,
    float* __restrict__ Hbuf,
    int* __restrict__ rbar) {
    __shared__ __align__(16) float hs[8 * HROW];
    __shared__ __align__(16) float zs[8 * 64];

    const int i  = blockIdx.x >> 4, j = blockIdx.x & 15;
    const int tid = threadIdx.x;
    const int w = tid >> 5, lane = tid & 31;
    const int c = lane & 7, kc = lane >> 3;
    const int k0 = kc * 64;
    const int pcol = 64 * j + 8 * w + c;
    const int orig = (pcol & 3) * 256 + (pcol >> 2);

    unsigned long long ureg[32];
#pragma unroll
    for (int m = 0; m < 32; m++) {
        float u0 = Ul[(size_t)(k0 + 2 * m) * FH + orig];
        float u1 = Ul[(size_t)(k0 + 2 * m + 1) * FH + orig];
        asm("mov.b64 %0, {%1, %2};" : "=l"(ureg[m]) : "f"(u0), "f"(u1));
    }

    const int b_l = lane & 7, u_l = lane >> 3;
    float cst = 0.f;
    int* bar = rbar + i * 32;

    float prer[8], pren[8];
    if (kc == 0) {
#pragma unroll
        for (int bi = 0; bi < 8; bi++)
            prer[bi] = pre[(size_t)(8 * i + bi) * FH + pcol];
    }

    for (int t = 0; t < Tn; t++) {
        if (t == 0) {
#pragma unroll
            for (int e = 0; e < 2; e++) {
                int qi = tid * 2 + e;
                int b = qi >> 6, k4 = qi & 63, col = 4 * k4;
                *(float4*)&hs[b * HROW + (col >> 6) * 72 + (col & 63)] =
                    make_float4(0.f, 0.f, 0.f, 0.f);
            }
        } else {
            const float* src = Hbuf + ((size_t)(t - 1) * Bn + 8 * i) * Hh;
#pragma unroll
            for (int e = 0; e < 2; e++) {
                int qi = tid * 2 + e;
                int b = qi >> 6, k4 = qi & 63, col = 4 * k4;
                float4 v = __ldcg((const float4*)(src + b * Hh + col));
                *(float4*)&hs[b * HROW + (col >> 6) * 72 + (col & 63)] = v;
            }
        }
        if (kc == 0 && t + 1 < Tn) {
#pragma unroll
            for (int bi = 0; bi < 8; bi++)
                pren[bi] = __ldcg(pre + ((size_t)(t + 1) * Bn + 8 * i + bi) * FH + pcol);
        }
        __syncthreads();

#pragma unroll
        for (int bi = 0; bi < 8; bi++) {
            const ulonglong2* hrow = (const ulonglong2*)&hs[bi * HROW + kc * 72];
            unsigned long long a0 = 0ull, a1 = 0ull;
#pragma unroll
            for (int m = 0; m < 16; m++) {
                ulonglong2 hv = hrow[m];
                fma2(a0, ureg[2 * m],     hv.x);
                fma2(a1, ureg[2 * m + 1], hv.y);
            }
            float2 p0 = unpk(a0), p1 = unpk(a1);
            float v = (p0.x + p0.y) + (p1.x + p1.y);
            v += __shfl_xor_sync(0xffffffffu, v, 8);
            v += __shfl_xor_sync(0xffffffffu, v, 16);
            if (kc == 0) zs[w * 64 + bi * 8 + c] = v + prer[bi];
        }
        if (kc == 0) {
#pragma unroll
            for (int bi = 0; bi < 8; bi++) prer[bi] = pren[bi];
        }
        __syncwarp();

        if (lane < 16) {
            float4 z4 = *(const float4*)&zs[w * 64 + b_l * 8 + u_l * 4];
            float ig = sigf(z4.x);
            float fg = sigf(z4.y);
            float gg = __tanhf(z4.z);
            float og = sigf(z4.w);
            cst = fg * cst + ig * gg;
            float h = og * __tanhf(cst);
            __stcg(&Hbuf[((size_t)t * Bn + 8 * i + b_l) * Hh + 16 * j + 2 * w + u_l], h);
        }
        __syncthreads();

        if (tid == 0) {
            asm volatile("red.release.gpu.global.add.s32 [%0], 1;"
                         :: "l"(bar) : "memory");
            int target = 16 * (t + 1), v;
            do {
                asm volatile("ld.relaxed.gpu.global.b32 %0, [%1];"
                             : "=r"(v) : "l"(bar) : "memory");
            } while (v < target);
            asm volatile("ld.acquire.gpu.global.b32 %0, [%1];"
                         : "=r"(v) : "l"(bar) : "memory");
        }
        __syncthreads();
    }
}

// rows of g_Y are in t*64+b order; out is [b][t]
__global__ void k_rowsum(float* __restrict__ out) {
    int row  = blockIdx.x * 8 + (threadIdx.x >> 5);
    int lane = threadIdx.x & 31;
    const float4* yr = (const float4*)(g_Y + (size_t)row * Hh);
    float4 a = yr[lane], b = yr[lane + 32];
    float s = a.x + a.y + a.z + a.w + b.x + b.y + b.z + b.w;
#pragma unroll
    for (int o = 16; o; o >>= 1) s += __shfl_xor_sync(0xffffffffu, s, o);
    if (!lane) out[(row & 63) * Tn + (row >> 6)] = s;
}

// ---------------- launch ----------------
extern "C" void kernel_launch(void* const* d_in, const int* in_sizes, int n_in,
                              void* d_out, int out_size) {
    const float* x     = (const float*)d_in[0];
    const float* delta = (const float*)d_in[1];
    const float* q     = (const float*)d_in[2];
    const float* Wx    = (const float*)d_in[3];
    const float* bx    = (const float*)d_in[4];
    const float* Wc    = (const float*)d_in[5];
    const float* bc    = (const float*)d_in[6];
    const float* Wd    = (const float*)d_in[7];
    const float* bd    = (const float*)d_in[8];
    const float* Wl    = (const float*)d_in[9];
    const float* Ul    = (const float*)d_in[10];
    const float* bl    = (const float*)d_in[11];
    const float* Wo    = (const float*)d_in[12];
    const float* bo    = (const float*)d_in[13];
    float* out = (float*)d_out;

    float *p_xc, *p_cl, *p_pre, *p_H, *p_Y, *p_WlP, *p_blP;
    int *p_bar;
    cudaGetSymbolAddress((void**)&p_xc,  g_xc);
    cudaGetSymbolAddress((void**)&p_cl,  g_cl);
    cudaGetSymbolAddress((void**)&p_pre, g_pre);
    cudaGetSymbolAddress((void**)&p_H,   g_H);
    cudaGetSymbolAddress((void**)&p_Y,   g_Y);
    cudaGetSymbolAddress((void**)&p_WlP, g_WlP);
    cudaGetSymbolAddress((void**)&p_blP, g_blP);
    cudaGetSymbolAddress((void**)&p_bar, g_rbar);

    k_reset<<<1, 256>>>();                                 // #1
    k_sums<<<BT / 8, 256>>>(x);                            // #2
    k_delta<<<BT / 256, 256>>>(delta, Wd, bd);             // #3
    // #4 (ncu slot): embed_x GEMM — measure the pipelining delta
    sgemm<0><<<dim3(BT / 128, 1), 256>>>(x, TWOK, Wx, En, p_xc, KXC, 0, bx, nullptr, TWOK);
    k_wlp<<<(KXC * FH + 255) / 256, 256>>>(Wl, bl);        // #5

    // count scan: one serial pass + parallel apply
    k_scanA<<<1024, 256>>>(x);
    k_Pt<<<2, 256>>>();
    k_carry<<<128, 256>>>();
    k_apply<<<BT * 128 / 256, 256>>>();

    // embed_count -> xc[:, 128:256]
    sgemm<0><<<dim3(BT / 128, 1), 256>>>(p_cl, TWOK, Wc, En, p_xc, KXC, 128, bc, nullptr, TWOK);
    // pre = xc @ WlP + blP, stored row-remapped to [t*64+b][FH]
    sgemm<2><<<dim3(BT / 128, FH / 128), 256>>>(p_xc, KXC, p_WlP, FH, p_pre, FH, 0, p_blP, nullptr, KXC);

    // sequential LSTM scan (R11 best config)
    k_lstm<<<128, 256>>>(Ul, p_pre, p_H, p_bar);

    // Y = sigmoid(H @ Wo + bo) * q   (rows in t*64+b order)
    sgemm<1><<<dim3(BT / 128, Hh / 128), 256>>>(p_H, Hh, Wo, Hh, p_Y, Hh, 0, bo, q, Hh);
    // out = rowsum(Y) with row remap
    k_rowsum<<<BT / 8, 256>>>(out);
}

// round 15
// speedup vs baseline: 1.5089x; 1.5089x over previous
#include <cuda_runtime.h>
#include <cstdint>
#include <math.h>

// Problem dims
#define Bn   64
#define Tn   1024
#define TWOK 512
#define En   128
#define Hh   256
#define FH   1024          // 4*H
#define BT   (Bn*Tn)       // 65536
#define KXC  272           // 2E+1 padded to multiple of 16 (tf32 BK)
#define HROW 288           // skewed h row stride (4 chunks of 72 floats)

// ---------------- packed fp32x2 / tf32 helpers ----------------
__device__ __forceinline__ void fma2(unsigned long long& acc,
                                     unsigned long long a,
                                     unsigned long long b) {
    asm("fma.rn.f32x2 %0, %1, %2, %0;" : "+l"(acc) : "l"(a), "l"(b));
}
__device__ __forceinline__ float2 unpk(unsigned long long v) {
    float2 r;
    asm("mov.b64 {%0, %1}, %2;" : "=f"(r.x), "=f"(r.y) : "l"(v));
    return r;
}
__device__ __forceinline__ float sigf(float x) {
    return fmaf(__tanhf(0.5f * x), 0.5f, 0.5f);
}
__device__ __forceinline__ unsigned cvt_tf32(float v) {
    unsigned r;
    asm("cvt.rna.tf32.f32 %0, %1;" : "=r"(r) : "f"(v));
    return r;
}
__device__ __forceinline__ void mma_tf32(float* d,
                                         unsigned a0, unsigned a1,
                                         unsigned a2, unsigned a3,
                                         unsigned b0, unsigned b1) {
    asm volatile(
        "mma.sync.aligned.m16n8k8.row.col.f32.tf32.tf32.f32 "
        "{%0,%1,%2,%3}, {%4,%5,%6,%7}, {%8,%9}, {%0,%1,%2,%3};"
        : "+f"(d[0]), "+f"(d[1]), "+f"(d[2]), "+f"(d[3])
        : "r"(a0), "r"(a1), "r"(a2), "r"(a3), "r"(b0), "r"(b1));
}

// ---------------- scratch (static device globals) ----------------
__device__ float g_s[BT];
__device__ float g_Pt[BT];
__device__ float g_Cin[Bn * 8 * TWOK];
__device__ float g_cl[(size_t)BT * TWOK];
__device__ float g_xc[(size_t)BT * KXC];
__device__ float g_WlP[KXC * FH];
__device__ float g_blP[FH];
__device__ float g_pre[(size_t)BT * FH];           // [t*64+b][FH] permuted cols
__device__ float g_H[(size_t)BT * Hh];             // [t][b][256] time-major
__device__ float g_Y[(size_t)BT * Hh];             // rows in t*64+b order
__device__ int   g_rbar[8 * 32];                   // row barriers (128B apart)

// ---------------- tiny kernels ----------------
__global__ void k_reset() {
    int i = threadIdx.x;
    if (i < 8 * 32) g_rbar[i] = 0;
}

__global__ void k_sums(const float* __restrict__ x) {
    int row  = blockIdx.x * 8 + (threadIdx.x >> 5);
    int lane = threadIdx.x & 31;
    const float4* xr = (const float4*)(x + (size_t)row * TWOK);
    float s = 0.f;
#pragma unroll
    for (int i = 0; i < 4; i++) {
        float4 v = xr[i * 32 + lane];
        s += v.x + v.y + v.z + v.w;
    }
#pragma unroll
    for (int o = 16; o; o >>= 1) s += __shfl_xor_sync(0xffffffffu, s, o);
    if (!lane) g_s[row] = s;
}

__global__ void k_delta(const float* __restrict__ delta,
                        const float* __restrict__ Wd,
                        const float* __restrict__ bd) {
    int i = blockIdx.x * 256 + threadIdx.x;
    float ed = expf(-(delta[i] * Wd[0] + bd[0]));
    float* xr = g_xc + (size_t)i * KXC;
    xr[256] = ed;
#pragma unroll
    for (int j = 257; j < KXC; j++) xr[j] = 0.f;
}

// ----- count scan: ONE serial pass + parallel apply -----
__global__ void k_scanA(const float* __restrict__ x) {
    int idx = blockIdx.x * 256 + threadIdx.x;
    int f = idx & 511, seg = (idx >> 9) & 7, b = idx >> 12;
    const float* sp = g_s + b * Tn + seg * 128;
    const float* xp = x    + ((size_t)b * Tn + seg * 128) * TWOK + f;
    float*       cp = g_cl + ((size_t)b * Tn + seg * 128) * TWOK + f;
    float c = 0.f;
#pragma unroll 4
    for (int tt = 0; tt < 128; tt++) {
        c = fmaf(sp[tt], c, xp[(size_t)tt * TWOK]);
        cp[(size_t)tt * TWOK] = c;
    }
}
__global__ void k_Pt() {
    int idx = blockIdx.x * 256 + threadIdx.x;
    if (idx >= Bn * 8) return;
    int b = idx >> 3, seg = idx & 7;
    const float* sp = g_s + b * Tn + seg * 128;
    float* pp = g_Pt + b * Tn + seg * 128;
    float p = 1.f;
    for (int tt = 0; tt < 128; tt++) { p *= sp[tt]; pp[tt] = p; }
}
__global__ void k_carry() {
    int idx = blockIdx.x * 256 + threadIdx.x;
    int b = idx >> 9, f = idx & 511;
    float c = 0.f;
#pragma unroll
    for (int j = 0; j < 8; j++) {
        g_Cin[(b * 8 + j) * 512 + f] = c;
        float P = g_Pt[b * Tn + j * 128 + 127];
        float Qe = g_cl[((size_t)b * Tn + j * 128 + 127) * TWOK + f];
        c = fmaf(P, c, Qe);
    }
}
__global__ void k_apply() {
    int gid = blockIdx.x * 256 + threadIdx.x;
    int row = gid >> 7, f4 = gid & 127;
    int b = row >> 10, t = row & 1023, seg = t >> 7;
    float A = g_Pt[row];
    float4* qp = (float4*)&g_cl[(size_t)row * TWOK + f4 * 4];
    float4 qv = *qp;
    float4 ci = *(const float4*)&g_Cin[((b << 3) + seg) * 512 + f4 * 4];
    qv.x = log1pf(fmaf(ci.x, A, qv.x));
    qv.y = log1pf(fmaf(ci.y, A, qv.y));
    qv.z = log1pf(fmaf(ci.z, A, qv.z));
    qv.w = log1pf(fmaf(ci.w, A, qv.w));
    *qp = qv;
}

__global__ void k_wlp(const float* __restrict__ Wl, const float* __restrict__ bl) {
    int i = blockIdx.x * 256 + threadIdx.x;
    if (i >= KXC * FH) return;
    int k = i / FH, jp = i % FH;
    int orig = (jp & 3) * 256 + (jp >> 2);
    g_WlP[i] = (k < 2 * En + 1) ? Wl[k * FH + orig] : 0.f;
    if (k == 0) g_blP[jp] = bl[orig];
}

// ---------------- tf32 tensor-core GEMM ----------------
// C[128x128 tile] = epi(A @ B + bias). 256 threads = 8 warps (2x4 warp grid),
// warp tile 64x32 = 4x4 m16n8k8 fragments. BK=16, double-buffered smem staged
// through cvt.rna.tf32. K multiple of 16. lda/ldb/cols multiples of 4.
// EPI 0: plain. EPI 1: sigmoid*q (rows t*64+b). EPI 2: row remap b*Tn+t -> t*64+b.
template <int EPI>
__global__ void __launch_bounds__(256) tgemm(
    const float* __restrict__ A, int lda,
    const float* __restrict__ Bm, int ldb,
    float* __restrict__ C, int ldc, int coff,
    const float* __restrict__ bias,
    const float* __restrict__ q,
    int K) {
    __shared__ __align__(16) unsigned As[2][16][132];
    __shared__ __align__(16) unsigned Bs[2][16][132];
    const int row0 = blockIdx.x * 128, col0 = blockIdx.y * 128;
    const int tid = threadIdx.x;
    const int w = tid >> 5, lane = tid & 31;
    const int g = lane >> 2, tg = lane & 3;
    const int wy = w >> 2, wx = w & 3;

    // staging maps
    const int arow = tid >> 2, akq = (tid & 3) * 4;        // A: rows arow, arow+64
    const int bk = tid >> 5, bcol = (tid & 31) * 4;        // B: k rows bk, bk+8

    const float* ApA = A + (size_t)(row0 + arow) * lda + akq;
    const float* ApB = A + (size_t)(row0 + arow + 64) * lda + akq;
    const float* Bp  = Bm + col0 + bcol;

    float d[4][4][4];
#pragma unroll
    for (int mf = 0; mf < 4; mf++)
#pragma unroll
        for (int nf = 0; nf < 4; nf++)
#pragma unroll
            for (int e = 0; e < 4; e++) d[mf][nf][e] = 0.f;

    // prologue: stage 0
    {
        float4 av0 = *(const float4*)ApA;
        float4 av1 = *(const float4*)ApB;
        float4 bv0 = *(const float4*)(Bp + (size_t)bk * ldb);
        float4 bv1 = *(const float4*)(Bp + (size_t)(bk + 8) * ldb);
        As[0][akq + 0][arow] = cvt_tf32(av0.x);
        As[0][akq + 1][arow] = cvt_tf32(av0.y);
        As[0][akq + 2][arow] = cvt_tf32(av0.z);
        As[0][akq + 3][arow] = cvt_tf32(av0.w);
        As[0][akq + 0][arow + 64] = cvt_tf32(av1.x);
        As[0][akq + 1][arow + 64] = cvt_tf32(av1.y);
        As[0][akq + 2][arow + 64] = cvt_tf32(av1.z);
        As[0][akq + 3][arow + 64] = cvt_tf32(av1.w);
        uint4 b0q = make_uint4(cvt_tf32(bv0.x), cvt_tf32(bv0.y),
                               cvt_tf32(bv0.z), cvt_tf32(bv0.w));
        uint4 b1q = make_uint4(cvt_tf32(bv1.x), cvt_tf32(bv1.y),
                               cvt_tf32(bv1.z), cvt_tf32(bv1.w));
        *(uint4*)&Bs[0][bk][bcol]     = b0q;
        *(uint4*)&Bs[0][bk + 8][bcol] = b1q;
    }
    __syncthreads();

    int buf = 0;
    for (int k0 = 0; k0 < K; k0 += 16) {
        const bool more = (k0 + 16 < K);
        float4 av0, av1, bv0, bv1;
        if (more) {
            av0 = *(const float4*)(ApA + k0 + 16);
            av1 = *(const float4*)(ApB + k0 + 16);
            bv0 = *(const float4*)(Bp + (size_t)(k0 + 16 + bk) * ldb);
            bv1 = *(const float4*)(Bp + (size_t)(k0 + 16 + bk + 8) * ldb);
        }
#pragma unroll
        for (int ks = 0; ks < 2; ks++) {
            unsigned af[4][4], bf[4][2];
            const int kp0 = ks * 8 + tg, kp1 = ks * 8 + tg + 4;
#pragma unroll
            for (int mf = 0; mf < 4; mf++) {
                int rb = wy * 64 + mf * 16 + g;
                af[mf][0] = As[buf][kp0][rb];
                af[mf][1] = As[buf][kp0][rb + 8];
                af[mf][2] = As[buf][kp1][rb];
                af[mf][3] = As[buf][kp1][rb + 8];
            }
#pragma unroll
            for (int nf = 0; nf < 4; nf++) {
                int cb = wx * 32 + nf * 8 + g;
                bf[nf][0] = Bs[buf][kp0][cb];
                bf[nf][1] = Bs[buf][kp1][cb];
            }
#pragma unroll
            for (int mf = 0; mf < 4; mf++)
#pragma unroll
                for (int nf = 0; nf < 4; nf++)
                    mma_tf32(d[mf][nf], af[mf][0], af[mf][1], af[mf][2], af[mf][3],
                             bf[nf][0], bf[nf][1]);
        }
        if (more) {
            int nb = buf ^ 1;
            As[nb][akq + 0][arow] = cvt_tf32(av0.x);
            As[nb][akq + 1][arow] = cvt_tf32(av0.y);
            As[nb][akq + 2][arow] = cvt_tf32(av0.z);
            As[nb][akq + 3][arow] = cvt_tf32(av0.w);
            As[nb][akq + 0][arow + 64] = cvt_tf32(av1.x);
            As[nb][akq + 1][arow + 64] = cvt_tf32(av1.y);
            As[nb][akq + 2][arow + 64] = cvt_tf32(av1.z);
            As[nb][akq + 3][arow + 64] = cvt_tf32(av1.w);
            uint4 b0q = make_uint4(cvt_tf32(bv0.x), cvt_tf32(bv0.y),
                                   cvt_tf32(bv0.z), cvt_tf32(bv0.w));
            uint4 b1q = make_uint4(cvt_tf32(bv1.x), cvt_tf32(bv1.y),
                                   cvt_tf32(bv1.z), cvt_tf32(bv1.w));
            *(uint4*)&Bs[nb][bk][bcol]     = b0q;
            *(uint4*)&Bs[nb][bk + 8][bcol] = b1q;
        }
        __syncthreads();
        buf ^= 1;
    }

    // epilogue
#pragma unroll
    for (int mf = 0; mf < 4; mf++) {
#pragma unroll
        for (int half = 0; half < 2; half++) {
            size_t r = (size_t)row0 + wy * 64 + mf * 16 + g + half * 8;
            size_t rout = r;
            if (EPI == 2) rout = ((r & 1023) << 6) + (r >> 10);
#pragma unroll
            for (int nf = 0; nf < 4; nf++) {
                int cc = col0 + wx * 32 + nf * 8 + 2 * tg;
                float v0 = d[mf][nf][half * 2 + 0] + bias[cc];
                float v1 = d[mf][nf][half * 2 + 1] + bias[cc + 1];
                if (EPI == 1) {
                    size_t qr = ((size_t)(r & 63) << 10) + (r >> 6);
                    v0 = q[qr * 256 + cc]     * sigf(v0);
                    v1 = q[qr * 256 + cc + 1] * sigf(v1);
                }
                *(float2*)&C[rout * ldc + coff + cc] = make_float2(v0, v1);
            }
        }
    }
}

// ---------------- persistent LSTM scan: R11 known-good (1-col, R9 barrier) ----------------
__global__ void __launch_bounds__(256, 1) k_lstm(
    const float* __restrict__ Ul,
    const float* __restrict__ pre,
    float* __restrict__ Hbuf,
    int* __restrict__ rbar) {
    __shared__ __align__(16) float hs[8 * HROW];
    __shared__ __align__(16) float zs[8 * 64];

    const int i  = blockIdx.x >> 4, j = blockIdx.x & 15;
    const int tid = threadIdx.x;
    const int w = tid >> 5, lane = tid & 31;
    const int c = lane & 7, kc = lane >> 3;
    const int k0 = kc * 64;
    const int pcol = 64 * j + 8 * w + c;
    const int orig = (pcol & 3) * 256 + (pcol >> 2);

    unsigned long long ureg[32];
#pragma unroll
    for (int m = 0; m < 32; m++) {
        float u0 = Ul[(size_t)(k0 + 2 * m) * FH + orig];
        float u1 = Ul[(size_t)(k0 + 2 * m + 1) * FH + orig];
        asm("mov.b64 %0, {%1, %2};" : "=l"(ureg[m]) : "f"(u0), "f"(u1));
    }

    const int b_l = lane & 7, u_l = lane >> 3;
    float cst = 0.f;
    int* bar = rbar + i * 32;

    float prer[8], pren[8];
    if (kc == 0) {
#pragma unroll
        for (int bi = 0; bi < 8; bi++)
            prer[bi] = pre[(size_t)(8 * i + bi) * FH + pcol];
    }

    for (int t = 0; t < Tn; t++) {
        if (t == 0) {
#pragma unroll
            for (int e = 0; e < 2; e++) {
                int qi = tid * 2 + e;
                int b = qi >> 6, k4 = qi & 63, col = 4 * k4;
                *(float4*)&hs[b * HROW + (col >> 6) * 72 + (col & 63)] =
                    make_float4(0.f, 0.f, 0.f, 0.f);
            }
        } else {
            const float* src = Hbuf + ((size_t)(t - 1) * Bn + 8 * i) * Hh;
#pragma unroll
            for (int e = 0; e < 2; e++) {
                int qi = tid * 2 + e;
                int b = qi >> 6, k4 = qi & 63, col = 4 * k4;
                float4 v = __ldcg((const float4*)(src + b * Hh + col));
                *(float4*)&hs[b * HROW + (col >> 6) * 72 + (col & 63)] = v;
            }
        }
        if (kc == 0 && t + 1 < Tn) {
#pragma unroll
            for (int bi = 0; bi < 8; bi++)
                pren[bi] = __ldcg(pre + ((size_t)(t + 1) * Bn + 8 * i + bi) * FH + pcol);
        }
        __syncthreads();

#pragma unroll
        for (int bi = 0; bi < 8; bi++) {
            const ulonglong2* hrow = (const ulonglong2*)&hs[bi * HROW + kc * 72];
            unsigned long long a0 = 0ull, a1 = 0ull;
#pragma unroll
            for (int m = 0; m < 16; m++) {
                ulonglong2 hv = hrow[m];
                fma2(a0, ureg[2 * m],     hv.x);
                fma2(a1, ureg[2 * m + 1], hv.y);
            }
            float2 p0 = unpk(a0), p1 = unpk(a1);
            float v = (p0.x + p0.y) + (p1.x + p1.y);
            v += __shfl_xor_sync(0xffffffffu, v, 8);
            v += __shfl_xor_sync(0xffffffffu, v, 16);
            if (kc == 0) zs[w * 64 + bi * 8 + c] = v + prer[bi];
        }
        if (kc == 0) {
#pragma unroll
            for (int bi = 0; bi < 8; bi++) prer[bi] = pren[bi];
        }
        __syncwarp();

        if (lane < 16) {
            float4 z4 = *(const float4*)&zs[w * 64 + b_l * 8 + u_l * 4];
            float ig = sigf(z4.x);
            float fg = sigf(z4.y);
            float gg = __tanhf(z4.z);
            float og = sigf(z4.w);
            cst = fg * cst + ig * gg;
            float h = og * __tanhf(cst);
            __stcg(&Hbuf[((size_t)t * Bn + 8 * i + b_l) * Hh + 16 * j + 2 * w + u_l], h);
        }
        __syncthreads();

        if (tid == 0) {
            asm volatile("red.release.gpu.global.add.s32 [%0], 1;"
                         :: "l"(bar) : "memory");
            int target = 16 * (t + 1), v;
            do {
                asm volatile("ld.relaxed.gpu.global.b32 %0, [%1];"
                             : "=r"(v) : "l"(bar) : "memory");
            } while (v < target);
            asm volatile("ld.acquire.gpu.global.b32 %0, [%1];"
                         : "=r"(v) : "l"(bar) : "memory");
        }
        __syncthreads();
    }
}

// rows of g_Y are in t*64+b order; out is [b][t]
__global__ void k_rowsum(float* __restrict__ out) {
    int row  = blockIdx.x * 8 + (threadIdx.x >> 5);
    int lane = threadIdx.x & 31;
    const float4* yr = (const float4*)(g_Y + (size_t)row * Hh);
    float4 a = yr[lane], b = yr[lane + 32];
    float s = a.x + a.y + a.z + a.w + b.x + b.y + b.z + b.w;
#pragma unroll
    for (int o = 16; o; o >>= 1) s += __shfl_xor_sync(0xffffffffu, s, o);
    if (!lane) out[(row & 63) * Tn + (row >> 6)] = s;
}

// ---------------- launch ----------------
extern "C" void kernel_launch(void* const* d_in, const int* in_sizes, int n_in,
                              void* d_out, int out_size) {
    const float* x     = (const float*)d_in[0];
    const float* delta = (const float*)d_in[1];
    const float* q     = (const float*)d_in[2];
    const float* Wx    = (const float*)d_in[3];
    const float* bx    = (const float*)d_in[4];
    const float* Wc    = (const float*)d_in[5];
    const float* bc    = (const float*)d_in[6];
    const float* Wd    = (const float*)d_in[7];
    const float* bd    = (const float*)d_in[8];
    const float* Wl    = (const float*)d_in[9];
    const float* Ul    = (const float*)d_in[10];
    const float* bl    = (const float*)d_in[11];
    const float* Wo    = (const float*)d_in[12];
    const float* bo    = (const float*)d_in[13];
    float* out = (float*)d_out;

    float *p_xc, *p_cl, *p_pre, *p_H, *p_Y, *p_WlP, *p_blP;
    int *p_bar;
    cudaGetSymbolAddress((void**)&p_xc,  g_xc);
    cudaGetSymbolAddress((void**)&p_cl,  g_cl);
    cudaGetSymbolAddress((void**)&p_pre, g_pre);
    cudaGetSymbolAddress((void**)&p_H,   g_H);
    cudaGetSymbolAddress((void**)&p_Y,   g_Y);
    cudaGetSymbolAddress((void**)&p_WlP, g_WlP);
    cudaGetSymbolAddress((void**)&p_blP, g_blP);
    cudaGetSymbolAddress((void**)&p_bar, g_rbar);

    k_reset<<<1, 256>>>();                                 // #1
    k_sums<<<BT / 8, 256>>>(x);                            // #2
    k_delta<<<BT / 256, 256>>>(delta, Wd, bd);             // #3
    // #4 (ncu slot): embed_x GEMM on tensor cores — measure the tf32 delta
    tgemm<0><<<dim3(BT / 128, 1), 256>>>(x, TWOK, Wx, En, p_xc, KXC, 0, bx, nullptr, TWOK);
    k_wlp<<<(KXC * FH + 255) / 256, 256>>>(Wl, bl);        // #5

    // count scan: one serial pass + parallel apply
    k_scanA<<<1024, 256>>>(x);
    k_Pt<<<2, 256>>>();
    k_carry<<<128, 256>>>();
    k_apply<<<BT * 128 / 256, 256>>>();

    // embed_count -> xc[:, 128:256]
    tgemm<0><<<dim3(BT / 128, 1), 256>>>(p_cl, TWOK, Wc, En, p_xc, KXC, 128, bc, nullptr, TWOK);
    // pre = xc @ WlP + blP, stored row-remapped to [t*64+b][FH]
    tgemm<2><<<dim3(BT / 128, FH / 128), 256>>>(p_xc, KXC, p_WlP, FH, p_pre, FH, 0, p_blP, nullptr, KXC);

    // sequential LSTM scan (R11 best config)
    k_lstm<<<128, 256>>>(Ul, p_pre, p_H, p_bar);

    // Y = sigmoid(H @ Wo + bo) * q   (rows in t*64+b order)
    tgemm<1><<<dim3(BT / 128, Hh / 128), 256>>>(p_H, Hh, Wo, Hh, p_Y, Hh, 0, bo, q, Hh);
    // out = rowsum(Y) with row remap
    k_rowsum<<<BT / 8, 256>>>(out);
}

// round 16
// speedup vs baseline: 1.6684x; 1.1057x over previous
#include <cuda_runtime.h>
#include <cstdint>
#include <math.h>

// Problem dims
#define Bn   64
#define Tn   1024
#define TWOK 512
#define En   128
#define Hh   256
#define FH   1024          // 4*H
#define BT   (Bn*Tn)       // 65536
#define KXC  272           // 2E+1 padded to multiple of 16 (tf32 BK)
#define PROBE_T 32

// ---------------- helpers ----------------
__device__ __forceinline__ float sigf(float x) {
    return fmaf(__tanhf(0.5f * x), 0.5f, 0.5f);
}
__device__ __forceinline__ unsigned cvt_tf32(float v) {
    unsigned r;
    asm("cvt.rna.tf32.f32 %0, %1;" : "=r"(r) : "f"(v));
    return r;
}
__device__ __forceinline__ void mma_tf32(float* d,
                                         unsigned a0, unsigned a1,
                                         unsigned a2, unsigned a3,
                                         unsigned b0, unsigned b1) {
    asm volatile(
        "mma.sync.aligned.m16n8k8.row.col.f32.tf32.tf32.f32 "
        "{%0,%1,%2,%3}, {%4,%5,%6,%7}, {%8,%9}, {%0,%1,%2,%3};"
        : "+f"(d[0]), "+f"(d[1]), "+f"(d[2]), "+f"(d[3])
        : "r"(a0), "r"(a1), "r"(a2), "r"(a3), "r"(b0), "r"(b1));
}

// ---------------- scratch (static device globals) ----------------
__device__ float g_s[BT];
__device__ float g_Pt[BT];
__device__ float g_Cin[Bn * 8 * TWOK];
__device__ float g_cl[(size_t)BT * TWOK];
__device__ float g_xc[(size_t)BT * KXC];
__device__ float g_WlP[KXC * FH];
__device__ float g_blP[FH];
__device__ float g_pre[(size_t)BT * FH];           // [t*64+b][FH] permuted cols
__device__ float g_H[(size_t)BT * Hh];             // [t][b][256] time-major
__device__ float g_Hp[(size_t)PROBE_T * Bn * Hh];  // probe h buffer
__device__ float g_Y[(size_t)BT * Hh];             // rows in t*64+b order
__device__ int   g_rbar[8 * 32];                   // row barriers (128B apart)
__device__ int   g_rbar2[8 * 32];                  // probe row barriers

// ---------------- tiny kernels ----------------
__global__ void k_reset() {
    int i = threadIdx.x;
    if (i < 8 * 32) { g_rbar[i] = 0; g_rbar2[i] = 0; }
}

__global__ void k_sums(const float* __restrict__ x) {
    int row  = blockIdx.x * 8 + (threadIdx.x >> 5);
    int lane = threadIdx.x & 31;
    const float4* xr = (const float4*)(x + (size_t)row * TWOK);
    float s = 0.f;
#pragma unroll
    for (int i = 0; i < 4; i++) {
        float4 v = xr[i * 32 + lane];
        s += v.x + v.y + v.z + v.w;
    }
#pragma unroll
    for (int o = 16; o; o >>= 1) s += __shfl_xor_sync(0xffffffffu, s, o);
    if (!lane) g_s[row] = s;
}

__global__ void k_delta(const float* __restrict__ delta,
                        const float* __restrict__ Wd,
                        const float* __restrict__ bd) {
    int i = blockIdx.x * 256 + threadIdx.x;
    float ed = expf(-(delta[i] * Wd[0] + bd[0]));
    float* xr = g_xc + (size_t)i * KXC;
    xr[256] = ed;
#pragma unroll
    for (int j = 257; j < KXC; j++) xr[j] = 0.f;
}

// ----- count scan: ONE serial pass + parallel apply -----
__global__ void k_scanA(const float* __restrict__ x) {
    int idx = blockIdx.x * 256 + threadIdx.x;
    int f = idx & 511, seg = (idx >> 9) & 7, b = idx >> 12;
    const float* sp = g_s + b * Tn + seg * 128;
    const float* xp = x    + ((size_t)b * Tn + seg * 128) * TWOK + f;
    float*       cp = g_cl + ((size_t)b * Tn + seg * 128) * TWOK + f;
    float c = 0.f;
#pragma unroll 4
    for (int tt = 0; tt < 128; tt++) {
        c = fmaf(sp[tt], c, xp[(size_t)tt * TWOK]);
        cp[(size_t)tt * TWOK] = c;
    }
}
__global__ void k_Pt() {
    int idx = blockIdx.x * 256 + threadIdx.x;
    if (idx >= Bn * 8) return;
    int b = idx >> 3, seg = idx & 7;
    const float* sp = g_s + b * Tn + seg * 128;
    float* pp = g_Pt + b * Tn + seg * 128;
    float p = 1.f;
    for (int tt = 0; tt < 128; tt++) { p *= sp[tt]; pp[tt] = p; }
}
__global__ void k_carry() {
    int idx = blockIdx.x * 256 + threadIdx.x;
    int b = idx >> 9, f = idx & 511;
    float c = 0.f;
#pragma unroll
    for (int j = 0; j < 8; j++) {
        g_Cin[(b * 8 + j) * 512 + f] = c;
        float P = g_Pt[b * Tn + j * 128 + 127];
        float Qe = g_cl[((size_t)b * Tn + j * 128 + 127) * TWOK + f];
        c = fmaf(P, c, Qe);
    }
}
__global__ void k_apply() {
    int gid = blockIdx.x * 256 + threadIdx.x;
    int row = gid >> 7, f4 = gid & 127;
    int b = row >> 10, t = row & 1023, seg = t >> 7;
    float A = g_Pt[row];
    float4* qp = (float4*)&g_cl[(size_t)row * TWOK + f4 * 4];
    float4 qv = *qp;
    float4 ci = *(const float4*)&g_Cin[((b << 3) + seg) * 512 + f4 * 4];
    qv.x = log1pf(fmaf(ci.x, A, qv.x));
    qv.y = log1pf(fmaf(ci.y, A, qv.y));
    qv.z = log1pf(fmaf(ci.z, A, qv.z));
    qv.w = log1pf(fmaf(ci.w, A, qv.w));
    *qp = qv;
}

__global__ void k_wlp(const float* __restrict__ Wl, const float* __restrict__ bl) {
    int i = blockIdx.x * 256 + threadIdx.x;
    if (i >= KXC * FH) return;
    int k = i / FH, jp = i % FH;
    int orig = (jp & 3) * 256 + (jp >> 2);
    g_WlP[i] = (k < 2 * En + 1) ? Wl[k * FH + orig] : 0.f;
    if (k == 0) g_blP[jp] = bl[orig];
}

// ---------------- tf32 tensor-core GEMM (R15 known-good) ----------------
template <int EPI>
__global__ void __launch_bounds__(256) tgemm(
    const float* __restrict__ A, int lda,
    const float* __restrict__ Bm, int ldb,
    float* __restrict__ C, int ldc, int coff,
    const float* __restrict__ bias,
    const float* __restrict__ q,
    int K) {
    __shared__ __align__(16) unsigned As[2][16][132];
    __shared__ __align__(16) unsigned Bs[2][16][132];
    const int row0 = blockIdx.x * 128, col0 = blockIdx.y * 128;
    const int tid = threadIdx.x;
    const int w = tid >> 5, lane = tid & 31;
    const int g = lane >> 2, tg = lane & 3;
    const int wy = w >> 2, wx = w & 3;

    const int arow = tid >> 2, akq = (tid & 3) * 4;
    const int bk = tid >> 5, bcol = (tid & 31) * 4;

    const float* ApA = A + (size_t)(row0 + arow) * lda + akq;
    const float* ApB = A + (size_t)(row0 + arow + 64) * lda + akq;
    const float* Bp  = Bm + col0 + bcol;

    float d[4][4][4];
#pragma unroll
    for (int mf = 0; mf < 4; mf++)
#pragma unroll
        for (int nf = 0; nf < 4; nf++)
#pragma unroll
            for (int e = 0; e < 4; e++) d[mf][nf][e] = 0.f;

    {
        float4 av0 = *(const float4*)ApA;
        float4 av1 = *(const float4*)ApB;
        float4 bv0 = *(const float4*)(Bp + (size_t)bk * ldb);
        float4 bv1 = *(const float4*)(Bp + (size_t)(bk + 8) * ldb);
        As[0][akq + 0][arow] = cvt_tf32(av0.x);
        As[0][akq + 1][arow] = cvt_tf32(av0.y);
        As[0][akq + 2][arow] = cvt_tf32(av0.z);
        As[0][akq + 3][arow] = cvt_tf32(av0.w);
        As[0][akq + 0][arow + 64] = cvt_tf32(av1.x);
        As[0][akq + 1][arow + 64] = cvt_tf32(av1.y);
        As[0][akq + 2][arow + 64] = cvt_tf32(av1.z);
        As[0][akq + 3][arow + 64] = cvt_tf32(av1.w);
        uint4 b0q = make_uint4(cvt_tf32(bv0.x), cvt_tf32(bv0.y),
                               cvt_tf32(bv0.z), cvt_tf32(bv0.w));
        uint4 b1q = make_uint4(cvt_tf32(bv1.x), cvt_tf32(bv1.y),
                               cvt_tf32(bv1.z), cvt_tf32(bv1.w));
        *(uint4*)&Bs[0][bk][bcol]     = b0q;
        *(uint4*)&Bs[0][bk + 8][bcol] = b1q;
    }
    __syncthreads();

    int buf = 0;
    for (int k0 = 0; k0 < K; k0 += 16) {
        const bool more = (k0 + 16 < K);
        float4 av0, av1, bv0, bv1;
        if (more) {
            av0 = *(const float4*)(ApA + k0 + 16);
            av1 = *(const float4*)(ApB + k0 + 16);
            bv0 = *(const float4*)(Bp + (size_t)(k0 + 16 + bk) * ldb);
            bv1 = *(const float4*)(Bp + (size_t)(k0 + 16 + bk + 8) * ldb);
        }
#pragma unroll
        for (int ks = 0; ks < 2; ks++) {
            unsigned af[4][4], bf[4][2];
            const int kp0 = ks * 8 + tg, kp1 = ks * 8 + tg + 4;
#pragma unroll
            for (int mf = 0; mf < 4; mf++) {
                int rb = wy * 64 + mf * 16 + g;
                af[mf][0] = As[buf][kp0][rb];
                af[mf][1] = As[buf][kp0][rb + 8];
                af[mf][2] = As[buf][kp1][rb];
                af[mf][3] = As[buf][kp1][rb + 8];
            }
#pragma unroll
            for (int nf = 0; nf < 4; nf++) {
                int cb = wx * 32 + nf * 8 + g;
                bf[nf][0] = Bs[buf][kp0][cb];
                bf[nf][1] = Bs[buf][kp1][cb];
            }
#pragma unroll
            for (int mf = 0; mf < 4; mf++)
#pragma unroll
                for (int nf = 0; nf < 4; nf++)
                    mma_tf32(d[mf][nf], af[mf][0], af[mf][1], af[mf][2], af[mf][3],
                             bf[nf][0], bf[nf][1]);
        }
        if (more) {
            int nb = buf ^ 1;
            As[nb][akq + 0][arow] = cvt_tf32(av0.x);
            As[nb][akq + 1][arow] = cvt_tf32(av0.y);
            As[nb][akq + 2][arow] = cvt_tf32(av0.z);
            As[nb][akq + 3][arow] = cvt_tf32(av0.w);
            As[nb][akq + 0][arow + 64] = cvt_tf32(av1.x);
            As[nb][akq + 1][arow + 64] = cvt_tf32(av1.y);
            As[nb][akq + 2][arow + 64] = cvt_tf32(av1.z);
            As[nb][akq + 3][arow + 64] = cvt_tf32(av1.w);
            uint4 b0q = make_uint4(cvt_tf32(bv0.x), cvt_tf32(bv0.y),
                                   cvt_tf32(bv0.z), cvt_tf32(bv0.w));
            uint4 b1q = make_uint4(cvt_tf32(bv1.x), cvt_tf32(bv1.y),
                                   cvt_tf32(bv1.z), cvt_tf32(bv1.w));
            *(uint4*)&Bs[nb][bk][bcol]     = b0q;
            *(uint4*)&Bs[nb][bk + 8][bcol] = b1q;
        }
        __syncthreads();
        buf ^= 1;
    }

#pragma unroll
    for (int mf = 0; mf < 4; mf++) {
#pragma unroll
        for (int half = 0; half < 2; half++) {
            size_t r = (size_t)row0 + wy * 64 + mf * 16 + g + half * 8;
            size_t rout = r;
            if (EPI == 2) rout = ((r & 1023) << 6) + (r >> 10);
#pragma unroll
            for (int nf = 0; nf < 4; nf++) {
                int cc = col0 + wx * 32 + nf * 8 + 2 * tg;
                float v0 = d[mf][nf][half * 2 + 0] + bias[cc];
                float v1 = d[mf][nf][half * 2 + 1] + bias[cc + 1];
                if (EPI == 1) {
                    size_t qr = ((size_t)(r & 63) << 10) + (r >> 6);
                    v0 = q[qr * 256 + cc]     * sigf(v0);
                    v1 = q[qr * 256 + cc + 1] * sigf(v1);
                }
                *(float2*)&C[rout * ldc + coff + cc] = make_float2(v0, v1);
            }
        }
    }
}

// ---------------- tensor-core LSTM scan ----------------
// Grid 128 = 4 batch-groups (i) x 32 col-groups (j).
// CTA (i,j): batches [16i,16i+16), permuted cols [32j,32j+32) = units [8j,8j+8).
// Z[16x32] = h[16x256] @ U[256x32] via m16n8k8 tf32.
// Warp (k2=w>>2, n=w&3): k-half k2*128, col-tile 8n. U fragments in regs (loop-invariant).
// h staged as tf32 in smem stride 260 (fragment LDS bank = 4g+tg, conflict-free).
// Gates: 128 threads, one (batch,unit) each, fp32 state; pre added at gate time.
template <int STEPS>
__global__ void __launch_bounds__(256, 1) k_lstm_t(
    const float* __restrict__ Ul,
    const float* __restrict__ pre,
    float* __restrict__ Hbuf,
    int* __restrict__ rbar) {
    __shared__ __align__(16) unsigned hsm[16][260];   // tf32 h
    __shared__ __align__(16) float zred[4][32][4];    // k2=1 partials
    __shared__ __align__(16) float zs[16][36];        // z staging

    const int i = blockIdx.x >> 5, j = blockIdx.x & 31;
    const int tid = threadIdx.x;
    const int w = tid >> 5, lane = tid & 31;
    const int k2 = w >> 2, n = w & 3;
    const int g = lane >> 2, tg = lane & 3;

    // ---- U fragments: 16 ksteps x 2 regs, tf32, held for all steps ----
    const int pc = 32 * j + 8 * n + g;
    const int orig = (pc & 3) * 256 + (pc >> 2);
    unsigned uf0[16], uf1[16];
#pragma unroll
    for (int ks = 0; ks < 16; ks++) {
        int kb = k2 * 128 + ks * 8;
        uf0[ks] = cvt_tf32(Ul[(size_t)(kb + tg) * FH + orig]);
        uf1[ks] = cvt_tf32(Ul[(size_t)(kb + tg + 4) * FH + orig]);
    }

    // gate mapping (tid < 128): batch bb, unit uu
    const int bb = tid >> 3, uu = tid & 7;
    float cst = 0.f;
    int* bar = rbar + i * 32;

    float4 prer, pren;
    if (tid < 128)
        prer = *(const float4*)&pre[(size_t)(16 * i + bb) * FH + 32 * j + 4 * uu];

    // staging map: thread stages row = tid>>4, 16 floats at col0=(tid&15)*16
    const int srow = tid >> 4, scol = (tid & 15) * 16;

    for (int t = 0; t < STEPS; t++) {
        // ---- stage h_{t-1} -> tf32 smem ----
        if (t == 0) {
#pragma unroll
            for (int e = 0; e < 4; e++)
                *(uint4*)&hsm[srow][scol + 4 * e] = make_uint4(0u, 0u, 0u, 0u);
        } else {
            const float* src = Hbuf + ((size_t)(t - 1) * Bn + 16 * i) * Hh;
#pragma unroll
            for (int e = 0; e < 4; e++) {
                float4 v = __ldcg((const float4*)(src + srow * Hh + scol + 4 * e));
                *(uint4*)&hsm[srow][scol + 4 * e] =
                    make_uint4(cvt_tf32(v.x), cvt_tf32(v.y),
                               cvt_tf32(v.z), cvt_tf32(v.w));
            }
        }
        if (tid < 128 && t + 1 < STEPS)
            pren = *(const float4*)&pre[((size_t)(t + 1) * Bn + 16 * i + bb) * FH +
                                        32 * j + 4 * uu];
        __syncthreads();

        // ---- mma: 16 ksteps ----
        float d[4] = {0.f, 0.f, 0.f, 0.f};
#pragma unroll
        for (int ks = 0; ks < 16; ks++) {
            int kb = k2 * 128 + ks * 8;
            unsigned a0 = hsm[g][kb + tg];
            unsigned a1 = hsm[g + 8][kb + tg];
            unsigned a2 = hsm[g][kb + tg + 4];
            unsigned a3 = hsm[g + 8][kb + tg + 4];
            mma_tf32(d, a0, a1, a2, a3, uf0[ks], uf1[ks]);
        }

        // ---- reduce k2 halves ----
        if (k2 == 1) *(float4*)zred[n][lane] = make_float4(d[0], d[1], d[2], d[3]);
        __syncthreads();
        if (k2 == 0) {
            float4 p = *(const float4*)zred[n][lane];
            zs[g][8 * n + 2 * tg]         = d[0] + p.x;
            zs[g][8 * n + 2 * tg + 1]     = d[1] + p.y;
            zs[g + 8][8 * n + 2 * tg]     = d[2] + p.z;
            zs[g + 8][8 * n + 2 * tg + 1] = d[3] + p.w;
        }
        __syncthreads();

        // ---- gates (tid<128): one (batch bb, unit uu) ----
        if (tid < 128) {
            float4 z4 = *(const float4*)&zs[bb][4 * uu];
            z4.x += prer.x; z4.y += prer.y; z4.z += prer.z; z4.w += prer.w;
            float ig = sigf(z4.x);
            float fg = sigf(z4.y);
            float gg = __tanhf(z4.z);
            float og = sigf(z4.w);
            cst = fg * cst + ig * gg;
            float h = og * __tanhf(cst);
            __stcg(&Hbuf[((size_t)t * Bn + 16 * i + bb) * Hh + 8 * j + uu], h);
            prer = pren;
        }
        __syncthreads();

        // ---- row barrier: 32 CTA-granular arrivals per batch-group ----
        if (tid == 0) {
            asm volatile("red.release.gpu.global.add.s32 [%0], 1;"
                         :: "l"(bar) : "memory");
            int target = 32 * (t + 1), v;
            do {
                asm volatile("ld.relaxed.gpu.global.b32 %0, [%1];"
                             : "=r"(v) : "l"(bar) : "memory");
            } while (v < target);
            asm volatile("ld.acquire.gpu.global.b32 %0, [%1];"
                         : "=r"(v) : "l"(bar) : "memory");
        }
        __syncthreads();
    }
}

// rows of g_Y are in t*64+b order; out is [b][t]
__global__ void k_rowsum(float* __restrict__ out) {
    int row  = blockIdx.x * 8 + (threadIdx.x >> 5);
    int lane = threadIdx.x & 31;
    const float4* yr = (const float4*)(g_Y + (size_t)row * Hh);
    float4 a = yr[lane], b = yr[lane + 32];
    float s = a.x + a.y + a.z + a.w + b.x + b.y + b.z + b.w;
#pragma unroll
    for (int o = 16; o; o >>= 1) s += __shfl_xor_sync(0xffffffffu, s, o);
    if (!lane) out[(row & 63) * Tn + (row >> 6)] = s;
}

// ---------------- launch ----------------
extern "C" void kernel_launch(void* const* d_in, const int* in_sizes, int n_in,
                              void* d_out, int out_size) {
    const float* x     = (const float*)d_in[0];
    const float* delta = (const float*)d_in[1];
    const float* q     = (const float*)d_in[2];
    const float* Wx    = (const float*)d_in[3];
    const float* bx    = (const float*)d_in[4];
    const float* Wc    = (const float*)d_in[5];
    const float* bc    = (const float*)d_in[6];
    const float* Wd    = (const float*)d_in[7];
    const float* bd    = (const float*)d_in[8];
    const float* Wl    = (const float*)d_in[9];
    const float* Ul    = (const float*)d_in[10];
    const float* bl    = (const float*)d_in[11];
    const float* Wo    = (const float*)d_in[12];
    const float* bo    = (const float*)d_in[13];
    float* out = (float*)d_out;

    float *p_xc, *p_cl, *p_pre, *p_H, *p_Hp, *p_Y, *p_WlP, *p_blP;
    int *p_bar, *p_bar2;
    cudaGetSymbolAddress((void**)&p_xc,  g_xc);
    cudaGetSymbolAddress((void**)&p_cl,  g_cl);
    cudaGetSymbolAddress((void**)&p_pre, g_pre);
    cudaGetSymbolAddress((void**)&p_H,   g_H);
    cudaGetSymbolAddress((void**)&p_Hp,  g_Hp);
    cudaGetSymbolAddress((void**)&p_Y,   g_Y);
    cudaGetSymbolAddress((void**)&p_WlP, g_WlP);
    cudaGetSymbolAddress((void**)&p_blP, g_blP);
    cudaGetSymbolAddress((void**)&p_bar, g_rbar);
    cudaGetSymbolAddress((void**)&p_bar2, g_rbar2);

    k_reset<<<1, 256>>>();                                 // #1
    k_sums<<<BT / 8, 256>>>(x);                            // #2
    k_delta<<<BT / 256, 256>>>(delta, Wd, bd);             // #3
    // #4 (ncu slot): 32-step tensor-LSTM probe (stale g_pre; g_Hp scratch)
    k_lstm_t<PROBE_T><<<128, 256>>>(Ul, p_pre, p_Hp, p_bar2);
    k_wlp<<<(KXC * FH + 255) / 256, 256>>>(Wl, bl);        // #5

    // count scan: one serial pass + parallel apply
    k_scanA<<<1024, 256>>>(x);
    k_Pt<<<2, 256>>>();
    k_carry<<<128, 256>>>();
    k_apply<<<BT * 128 / 256, 256>>>();

    // embed_x -> xc[:, 0:128]
    tgemm<0><<<dim3(BT / 128, 1), 256>>>(x, TWOK, Wx, En, p_xc, KXC, 0, bx, nullptr, TWOK);
    // embed_count -> xc[:, 128:256]
    tgemm<0><<<dim3(BT / 128, 1), 256>>>(p_cl, TWOK, Wc, En, p_xc, KXC, 128, bc, nullptr, TWOK);
    // pre = xc @ WlP + blP, stored row-remapped to [t*64+b][FH]
    tgemm<2><<<dim3(BT / 128, FH / 128), 256>>>(p_xc, KXC, p_WlP, FH, p_pre, FH, 0, p_blP, nullptr, KXC);

    // sequential LSTM scan on tensor cores
    k_lstm_t<Tn><<<128, 256>>>(Ul, p_pre, p_H, p_bar);

    // Y = sigmoid(H @ Wo + bo) * q   (rows in t*64+b order)
    tgemm<1><<<dim3(BT / 128, Hh / 128), 256>>>(p_H, Hh, Wo, Hh, p_Y, Hh, 0, bo, q, Hh);
    // out = rowsum(Y) with row remap
    k_rowsum<<<BT / 8, 256>>>(out);
}

// round 17
// speedup vs baseline: 1.7190x; 1.0303x over previous
#include <cuda_runtime.h>
#include <cstdint>
#include <math.h>

// Problem dims
#define Bn   64
#define Tn   1024
#define TWOK 512
#define En   128
#define Hh   256
#define FH   1024          // 4*H
#define BT   (Bn*Tn)       // 65536
#define KXC  272           // 2E+1 padded to multiple of 16 (tf32 BK)
#define PROBE_T 32

// ---------------- helpers ----------------
__device__ __forceinline__ float sigf(float x) {
    return fmaf(__tanhf(0.5f * x), 0.5f, 0.5f);
}
__device__ __forceinline__ unsigned cvt_tf32(float v) {
    unsigned r;
    asm("cvt.rna.tf32.f32 %0, %1;" : "=r"(r) : "f"(v));
    return r;
}
__device__ __forceinline__ void mma_tf32(float* d,
                                         unsigned a0, unsigned a1,
                                         unsigned a2, unsigned a3,
                                         unsigned b0, unsigned b1) {
    asm volatile(
        "mma.sync.aligned.m16n8k8.row.col.f32.tf32.tf32.f32 "
        "{%0,%1,%2,%3}, {%4,%5,%6,%7}, {%8,%9}, {%0,%1,%2,%3};"
        : "+f"(d[0]), "+f"(d[1]), "+f"(d[2]), "+f"(d[3])
        : "r"(a0), "r"(a1), "r"(a2), "r"(a3), "r"(b0), "r"(b1));
}

// ---------------- scratch (static device globals) ----------------
__device__ float g_s[BT];
__device__ float g_Pt[BT];
__device__ float g_Cin[Bn * 8 * TWOK];
__device__ float g_cl[(size_t)BT * TWOK];
__device__ float g_xc[(size_t)BT * KXC];
__device__ float g_WlP[KXC * FH];
__device__ float g_blP[FH];
__device__ float g_pre[(size_t)BT * FH];           // [t*64+b][FH] permuted cols
__device__ float g_H[(size_t)BT * Hh];             // [t][b][256] time-major
__device__ float g_Hp[(size_t)PROBE_T * Bn * Hh];  // probe h buffer
__device__ float g_Y[(size_t)BT * Hh];             // rows in t*64+b order
__device__ int   g_rbar[8 * 32];                   // row barriers (128B apart)
__device__ int   g_rbar2[8 * 32];                  // probe row barriers

// ---------------- tiny kernels ----------------
__global__ void k_reset() {
    int i = threadIdx.x;
    if (i < 8 * 32) { g_rbar[i] = 0; g_rbar2[i] = 0; }
}

__global__ void k_sums(const float* __restrict__ x) {
    int row  = blockIdx.x * 8 + (threadIdx.x >> 5);
    int lane = threadIdx.x & 31;
    const float4* xr = (const float4*)(x + (size_t)row * TWOK);
    float s = 0.f;
#pragma unroll
    for (int i = 0; i < 4; i++) {
        float4 v = xr[i * 32 + lane];
        s += v.x + v.y + v.z + v.w;
    }
#pragma unroll
    for (int o = 16; o; o >>= 1) s += __shfl_xor_sync(0xffffffffu, s, o);
    if (!lane) g_s[row] = s;
}

__global__ void k_delta(const float* __restrict__ delta,
                        const float* __restrict__ Wd,
                        const float* __restrict__ bd) {
    int i = blockIdx.x * 256 + threadIdx.x;
    float ed = expf(-(delta[i] * Wd[0] + bd[0]));
    float* xr = g_xc + (size_t)i * KXC;
    xr[256] = ed;
#pragma unroll
    for (int j = 257; j < KXC; j++) xr[j] = 0.f;
}

// ----- count scan: ONE serial pass + parallel apply -----
__global__ void k_scanA(const float* __restrict__ x) {
    int idx = blockIdx.x * 256 + threadIdx.x;
    int f = idx & 511, seg = (idx >> 9) & 7, b = idx >> 12;
    const float* sp = g_s + b * Tn + seg * 128;
    const float* xp = x    + ((size_t)b * Tn + seg * 128) * TWOK + f;
    float*       cp = g_cl + ((size_t)b * Tn + seg * 128) * TWOK + f;
    float c = 0.f;
#pragma unroll 4
    for (int tt = 0; tt < 128; tt++) {
        c = fmaf(sp[tt], c, xp[(size_t)tt * TWOK]);
        cp[(size_t)tt * TWOK] = c;
    }
}
__global__ void k_Pt() {
    int idx = blockIdx.x * 256 + threadIdx.x;
    if (idx >= Bn * 8) return;
    int b = idx >> 3, seg = idx & 7;
    const float* sp = g_s + b * Tn + seg * 128;
    float* pp = g_Pt + b * Tn + seg * 128;
    float p = 1.f;
    for (int tt = 0; tt < 128; tt++) { p *= sp[tt]; pp[tt] = p; }
}
__global__ void k_carry() {
    int idx = blockIdx.x * 256 + threadIdx.x;
    int b = idx >> 9, f = idx & 511;
    float c = 0.f;
#pragma unroll
    for (int j = 0; j < 8; j++) {
        g_Cin[(b * 8 + j) * 512 + f] = c;
        float P = g_Pt[b * Tn + j * 128 + 127];
        float Qe = g_cl[((size_t)b * Tn + j * 128 + 127) * TWOK + f];
        c = fmaf(P, c, Qe);
    }
}
__global__ void k_apply() {
    int gid = blockIdx.x * 256 + threadIdx.x;
    int row = gid >> 7, f4 = gid & 127;
    int b = row >> 10, t = row & 1023, seg = t >> 7;
    float A = g_Pt[row];
    float4* qp = (float4*)&g_cl[(size_t)row * TWOK + f4 * 4];
    float4 qv = *qp;
    float4 ci = *(const float4*)&g_Cin[((b << 3) + seg) * 512 + f4 * 4];
    qv.x = log1pf(fmaf(ci.x, A, qv.x));
    qv.y = log1pf(fmaf(ci.y, A, qv.y));
    qv.z = log1pf(fmaf(ci.z, A, qv.z));
    qv.w = log1pf(fmaf(ci.w, A, qv.w));
    *qp = qv;
}

__global__ void k_wlp(const float* __restrict__ Wl, const float* __restrict__ bl) {
    int i = blockIdx.x * 256 + threadIdx.x;
    if (i >= KXC * FH) return;
    int k = i / FH, jp = i % FH;
    int orig = (jp & 3) * 256 + (jp >> 2);
    g_WlP[i] = (k < 2 * En + 1) ? Wl[k * FH + orig] : 0.f;
    if (k == 0) g_blP[jp] = bl[orig];
}

// ---------------- tf32 tensor-core GEMM (R15 known-good) ----------------
template <int EPI>
__global__ void __launch_bounds__(256) tgemm(
    const float* __restrict__ A, int lda,
    const float* __restrict__ Bm, int ldb,
    float* __restrict__ C, int ldc, int coff,
    const float* __restrict__ bias,
    const float* __restrict__ q,
    int K) {
    __shared__ __align__(16) unsigned As[2][16][132];
    __shared__ __align__(16) unsigned Bs[2][16][132];
    const int row0 = blockIdx.x * 128, col0 = blockIdx.y * 128;
    const int tid = threadIdx.x;
    const int w = tid >> 5, lane = tid & 31;
    const int g = lane >> 2, tg = lane & 3;
    const int wy = w >> 2, wx = w & 3;

    const int arow = tid >> 2, akq = (tid & 3) * 4;
    const int bk = tid >> 5, bcol = (tid & 31) * 4;

    const float* ApA = A + (size_t)(row0 + arow) * lda + akq;
    const float* ApB = A + (size_t)(row0 + arow + 64) * lda + akq;
    const float* Bp  = Bm + col0 + bcol;

    float d[4][4][4];
#pragma unroll
    for (int mf = 0; mf < 4; mf++)
#pragma unroll
        for (int nf = 0; nf < 4; nf++)
#pragma unroll
            for (int e = 0; e < 4; e++) d[mf][nf][e] = 0.f;

    {
        float4 av0 = *(const float4*)ApA;
        float4 av1 = *(const float4*)ApB;
        float4 bv0 = *(const float4*)(Bp + (size_t)bk * ldb);
        float4 bv1 = *(const float4*)(Bp + (size_t)(bk + 8) * ldb);
        As[0][akq + 0][arow] = cvt_tf32(av0.x);
        As[0][akq + 1][arow] = cvt_tf32(av0.y);
        As[0][akq + 2][arow] = cvt_tf32(av0.z);
        As[0][akq + 3][arow] = cvt_tf32(av0.w);
        As[0][akq + 0][arow + 64] = cvt_tf32(av1.x);
        As[0][akq + 1][arow + 64] = cvt_tf32(av1.y);
        As[0][akq + 2][arow + 64] = cvt_tf32(av1.z);
        As[0][akq + 3][arow + 64] = cvt_tf32(av1.w);
        uint4 b0q = make_uint4(cvt_tf32(bv0.x), cvt_tf32(bv0.y),
                               cvt_tf32(bv0.z), cvt_tf32(bv0.w));
        uint4 b1q = make_uint4(cvt_tf32(bv1.x), cvt_tf32(bv1.y),
                               cvt_tf32(bv1.z), cvt_tf32(bv1.w));
        *(uint4*)&Bs[0][bk][bcol]     = b0q;
        *(uint4*)&Bs[0][bk + 8][bcol] = b1q;
    }
    __syncthreads();

    int buf = 0;
    for (int k0 = 0; k0 < K; k0 += 16) {
        const bool more = (k0 + 16 < K);
        float4 av0, av1, bv0, bv1;
        if (more) {
            av0 = *(const float4*)(ApA + k0 + 16);
            av1 = *(const float4*)(ApB + k0 + 16);
            bv0 = *(const float4*)(Bp + (size_t)(k0 + 16 + bk) * ldb);
            bv1 = *(const float4*)(Bp + (size_t)(k0 + 16 + bk + 8) * ldb);
        }
#pragma unroll
        for (int ks = 0; ks < 2; ks++) {
            unsigned af[4][4], bf[4][2];
            const int kp0 = ks * 8 + tg, kp1 = ks * 8 + tg + 4;
#pragma unroll
            for (int mf = 0; mf < 4; mf++) {
                int rb = wy * 64 + mf * 16 + g;
                af[mf][0] = As[buf][kp0][rb];
                af[mf][1] = As[buf][kp0][rb + 8];
                af[mf][2] = As[buf][kp1][rb];
                af[mf][3] = As[buf][kp1][rb + 8];
            }
#pragma unroll
            for (int nf = 0; nf < 4; nf++) {
                int cb = wx * 32 + nf * 8 + g;
                bf[nf][0] = Bs[buf][kp0][cb];
                bf[nf][1] = Bs[buf][kp1][cb];
            }
#pragma unroll
            for (int mf = 0; mf < 4; mf++)
#pragma unroll
                for (int nf = 0; nf < 4; nf++)
                    mma_tf32(d[mf][nf], af[mf][0], af[mf][1], af[mf][2], af[mf][3],
                             bf[nf][0], bf[nf][1]);
        }
        if (more) {
            int nb = buf ^ 1;
            As[nb][akq + 0][arow] = cvt_tf32(av0.x);
            As[nb][akq + 1][arow] = cvt_tf32(av0.y);
            As[nb][akq + 2][arow] = cvt_tf32(av0.z);
            As[nb][akq + 3][arow] = cvt_tf32(av0.w);
            As[nb][akq + 0][arow + 64] = cvt_tf32(av1.x);
            As[nb][akq + 1][arow + 64] = cvt_tf32(av1.y);
            As[nb][akq + 2][arow + 64] = cvt_tf32(av1.z);
            As[nb][akq + 3][arow + 64] = cvt_tf32(av1.w);
            uint4 b0q = make_uint4(cvt_tf32(bv0.x), cvt_tf32(bv0.y),
                                   cvt_tf32(bv0.z), cvt_tf32(bv0.w));
            uint4 b1q = make_uint4(cvt_tf32(bv1.x), cvt_tf32(bv1.y),
                                   cvt_tf32(bv1.z), cvt_tf32(bv1.w));
            *(uint4*)&Bs[nb][bk][bcol]     = b0q;
            *(uint4*)&Bs[nb][bk + 8][bcol] = b1q;
        }
        __syncthreads();
        buf ^= 1;
    }

#pragma unroll
    for (int mf = 0; mf < 4; mf++) {
#pragma unroll
        for (int half = 0; half < 2; half++) {
            size_t r = (size_t)row0 + wy * 64 + mf * 16 + g + half * 8;
            size_t rout = r;
            if (EPI == 2) rout = ((r & 1023) << 6) + (r >> 10);
#pragma unroll
            for (int nf = 0; nf < 4; nf++) {
                int cc = col0 + wx * 32 + nf * 8 + 2 * tg;
                float v0 = d[mf][nf][half * 2 + 0] + bias[cc];
                float v1 = d[mf][nf][half * 2 + 1] + bias[cc + 1];
                if (EPI == 1) {
                    size_t qr = ((size_t)(r & 63) << 10) + (r >> 6);
                    v0 = q[qr * 256 + cc]     * sigf(v0);
                    v1 = q[qr * 256 + cc + 1] * sigf(v1);
                }
                *(float2*)&C[rout * ldc + coff + cc] = make_float2(v0, v1);
            }
        }
    }
}

// ---------------- tensor-core LSTM scan (dual-acc, shuffle gates) ----------------
// Grid 128 = 4 batch-groups (i) x 32 col-groups (j).
// CTA (i,j): batches [16i,16i+16), permuted cols [32j,32j+32) = units [8j,8j+8).
// Warp (k2=w>>2, n=w&3). U fragments in regs. Dual accumulators split the MMA
// RAW chain. Gates live in k2=0 warps: z gathered via 8 shfl (no zs smem, one
// fewer syncthreads). Lane L of k2=0 warp n: batch b=L>>1, unit 2n+(L&1).
template <int STEPS>
__global__ void __launch_bounds__(256, 1) k_lstm_t(
    const float* __restrict__ Ul,
    const float* __restrict__ pre,
    float* __restrict__ Hbuf,
    int* __restrict__ rbar) {
    __shared__ __align__(16) unsigned hsm[16][260];   // tf32 h
    __shared__ __align__(16) float zred[4][32][4];    // k2=1 partials

    const int i = blockIdx.x >> 5, j = blockIdx.x & 31;
    const int tid = threadIdx.x;
    const int w = tid >> 5, lane = tid & 31;
    const int k2 = w >> 2, n = w & 3;
    const int g = lane >> 2, tg = lane & 3;

    // ---- U fragments: 16 ksteps x 2 regs, tf32, held for all steps ----
    const int pc = 32 * j + 8 * n + g;
    const int orig = (pc & 3) * 256 + (pc >> 2);
    unsigned uf0[16], uf1[16];
#pragma unroll
    for (int ks = 0; ks < 16; ks++) {
        int kb = k2 * 128 + ks * 8;
        uf0[ks] = cvt_tf32(Ul[(size_t)(kb + tg) * FH + orig]);
        uf1[ks] = cvt_tf32(Ul[(size_t)(kb + tg + 4) * FH + orig]);
    }

    // gate mapping (k2==0 warps): batch b, sub-unit s; z gathered from lanes src0/src0+1
    const int b = lane >> 1, s = lane & 1;
    const int src0 = (b & 7) * 4 + 2 * s;
    const bool hi = (b >= 8);
    float cst = 0.f;
    int* bar = rbar + i * 32;

    float4 prer, pren;
    if (k2 == 0)
        prer = *(const float4*)&pre[(size_t)(16 * i + b) * FH + 32 * j + (2 * n + s) * 4];

    const int srow = tid >> 4, scol = (tid & 15) * 16;

    for (int t = 0; t < STEPS; t++) {
        // ---- stage h_{t-1} -> tf32 smem ----
        if (t == 0) {
#pragma unroll
            for (int e = 0; e < 4; e++)
                *(uint4*)&hsm[srow][scol + 4 * e] = make_uint4(0u, 0u, 0u, 0u);
        } else {
            const float* src = Hbuf + ((size_t)(t - 1) * Bn + 16 * i) * Hh;
#pragma unroll
            for (int e = 0; e < 4; e++) {
                float4 v = __ldcg((const float4*)(src + srow * Hh + scol + 4 * e));
                *(uint4*)&hsm[srow][scol + 4 * e] =
                    make_uint4(cvt_tf32(v.x), cvt_tf32(v.y),
                               cvt_tf32(v.z), cvt_tf32(v.w));
            }
        }
        if (k2 == 0 && t + 1 < STEPS)
            pren = *(const float4*)&pre[((size_t)(t + 1) * Bn + 16 * i + b) * FH +
                                        32 * j + (2 * n + s) * 4];
        __syncthreads();

        // ---- mma: 16 ksteps, dual accumulators (two independent 8-chains) ----
        float dA[4] = {0.f, 0.f, 0.f, 0.f};
        float dB[4] = {0.f, 0.f, 0.f, 0.f};
#pragma unroll
        for (int ks = 0; ks < 16; ks += 2) {
            int kb0 = k2 * 128 + ks * 8;
            int kb1 = kb0 + 8;
            mma_tf32(dA, hsm[g][kb0 + tg], hsm[g + 8][kb0 + tg],
                     hsm[g][kb0 + tg + 4], hsm[g + 8][kb0 + tg + 4],
                     uf0[ks], uf1[ks]);
            mma_tf32(dB, hsm[g][kb1 + tg], hsm[g + 8][kb1 + tg],
                     hsm[g][kb1 + tg + 4], hsm[g + 8][kb1 + tg + 4],
                     uf0[ks + 1], uf1[ks + 1]);
        }
        float d0 = dA[0] + dB[0], d1 = dA[1] + dB[1];
        float d2 = dA[2] + dB[2], d3 = dA[3] + dB[3];

        // ---- reduce k2 halves through smem ----
        if (k2 == 1) *(float4*)zred[n][lane] = make_float4(d0, d1, d2, d3);
        __syncthreads();

        // ---- gates fully in k2=0 warps via shuffles ----
        if (k2 == 0) {
            float4 p = *(const float4*)zred[n][lane];
            d0 += p.x; d1 += p.y; d2 += p.z; d3 += p.w;
            float x0 = __shfl_sync(0xffffffffu, d0, src0);
            float x1 = __shfl_sync(0xffffffffu, d1, src0);
            float x2 = __shfl_sync(0xffffffffu, d2, src0);
            float x3 = __shfl_sync(0xffffffffu, d3, src0);
            float y0 = __shfl_sync(0xffffffffu, d0, src0 + 1);
            float y1 = __shfl_sync(0xffffffffu, d1, src0 + 1);
            float y2 = __shfl_sync(0xffffffffu, d2, src0 + 1);
            float y3 = __shfl_sync(0xffffffffu, d3, src0 + 1);
            float zi = (hi ? x2 : x0) + prer.x;
            float zf = (hi ? x3 : x1) + prer.y;
            float zg = (hi ? y2 : y0) + prer.z;
            float zo = (hi ? y3 : y1) + prer.w;
            float ig = sigf(zi);
            float fg = sigf(zf);
            float gg = __tanhf(zg);
            float og = sigf(zo);
            cst = fg * cst + ig * gg;
            float h = og * __tanhf(cst);
            __stcg(&Hbuf[((size_t)t * Bn + 16 * i + b) * Hh + 8 * j + 2 * n + s], h);
            prer = pren;
        }
        __syncthreads();

        // ---- row barrier: 32 CTA-granular arrivals per batch-group ----
        if (tid == 0) {
            asm volatile("red.release.gpu.global.add.s32 [%0], 1;"
                         :: "l"(bar) : "memory");
            int target = 32 * (t + 1), v;
            do {
                asm volatile("ld.relaxed.gpu.global.b32 %0, [%1];"
                             : "=r"(v) : "l"(bar) : "memory");
            } while (v < target);
            asm volatile("ld.acquire.gpu.global.b32 %0, [%1];"
                         : "=r"(v) : "l"(bar) : "memory");
        }
        __syncthreads();
    }
}

// rows of g_Y are in t*64+b order; out is [b][t]
__global__ void k_rowsum(float* __restrict__ out) {
    int row  = blockIdx.x * 8 + (threadIdx.x >> 5);
    int lane = threadIdx.x & 31;
    const float4* yr = (const float4*)(g_Y + (size_t)row * Hh);
    float4 a = yr[lane], b = yr[lane + 32];
    float s = a.x + a.y + a.z + a.w + b.x + b.y + b.z + b.w;
#pragma unroll
    for (int o = 16; o; o >>= 1) s += __shfl_xor_sync(0xffffffffu, s, o);
    if (!lane) out[(row & 63) * Tn + (row >> 6)] = s;
}

// ---------------- launch ----------------
extern "C" void kernel_launch(void* const* d_in, const int* in_sizes, int n_in,
                              void* d_out, int out_size) {
    const float* x     = (const float*)d_in[0];
    const float* delta = (const float*)d_in[1];
    const float* q     = (const float*)d_in[2];
    const float* Wx    = (const float*)d_in[3];
    const float* bx    = (const float*)d_in[4];
    const float* Wc    = (const float*)d_in[5];
    const float* bc    = (const float*)d_in[6];
    const float* Wd    = (const float*)d_in[7];
    const float* bd    = (const float*)d_in[8];
    const float* Wl    = (const float*)d_in[9];
    const float* Ul    = (const float*)d_in[10];
    const float* bl    = (const float*)d_in[11];
    const float* Wo    = (const float*)d_in[12];
    const float* bo    = (const float*)d_in[13];
    float* out = (float*)d_out;

    float *p_xc, *p_cl, *p_pre, *p_H, *p_Hp, *p_Y, *p_WlP, *p_blP;
    int *p_bar, *p_bar2;
    cudaGetSymbolAddress((void**)&p_xc,  g_xc);
    cudaGetSymbolAddress((void**)&p_cl,  g_cl);
    cudaGetSymbolAddress((void**)&p_pre, g_pre);
    cudaGetSymbolAddress((void**)&p_H,   g_H);
    cudaGetSymbolAddress((void**)&p_Hp,  g_Hp);
    cudaGetSymbolAddress((void**)&p_Y,   g_Y);
    cudaGetSymbolAddress((void**)&p_WlP, g_WlP);
    cudaGetSymbolAddress((void**)&p_blP, g_blP);
    cudaGetSymbolAddress((void**)&p_bar, g_rbar);
    cudaGetSymbolAddress((void**)&p_bar2, g_rbar2);

    k_reset<<<1, 256>>>();                                 // #1
    k_sums<<<BT / 8, 256>>>(x);                            // #2
    k_delta<<<BT / 256, 256>>>(delta, Wd, bd);             // #3
    // #4 (ncu slot): 32-step tensor-LSTM probe (stale g_pre; g_Hp scratch)
    k_lstm_t<PROBE_T><<<128, 256>>>(Ul, p_pre, p_Hp, p_bar2);
    k_wlp<<<(KXC * FH + 255) / 256, 256>>>(Wl, bl);        // #5

    // count scan: one serial pass + parallel apply
    k_scanA<<<1024, 256>>>(x);
    k_Pt<<<2, 256>>>();
    k_carry<<<128, 256>>>();
    k_apply<<<BT * 128 / 256, 256>>>();

    // embed_x -> xc[:, 0:128]
    tgemm<0><<<dim3(BT / 128, 1), 256>>>(x, TWOK, Wx, En, p_xc, KXC, 0, bx, nullptr, TWOK);
    // embed_count -> xc[:, 128:256]
    tgemm<0><<<dim3(BT / 128, 1), 256>>>(p_cl, TWOK, Wc, En, p_xc, KXC, 128, bc, nullptr, TWOK);
    // pre = xc @ WlP + blP, stored row-remapped to [t*64+b][FH]
    tgemm<2><<<dim3(BT / 128, FH / 128), 256>>>(p_xc, KXC, p_WlP, FH, p_pre, FH, 0, p_blP, nullptr, KXC);

    // sequential LSTM scan on tensor cores
    k_lstm_t<Tn><<<128, 256>>>(Ul, p_pre, p_H, p_bar);

    // Y = sigmoid(H @ Wo + bo) * q   (rows in t*64+b order)
    tgemm<1><<<dim3(BT / 128, Hh / 128), 256>>>(p_H, Hh, Wo, Hh, p_Y, Hh, 0, bo, q, Hh);
    // out = rowsum(Y) with row remap
    k_rowsum<<<BT / 8, 256>>>(out);
}